// round 2
// baseline (speedup 1.0000x reference)
#include <cuda_runtime.h>
#include <math_constants.h>

#define BB 2
#define HH 8
#define LL 2048
#define DD 64
#define CC 512
#define NQ 16
#define NK 32
#define BLKQ 128
#define BLKK 64

// ---------------- scratch (no allocations allowed) ----------------
__device__ float g_q[BB*HH*LL*DD];
__device__ float g_k[BB*HH*LL*DD];
__device__ float g_v[BB*HH*LL*DD];
__device__ float g_qm[BB*HH*NQ*DD];
__device__ float g_km[BB*HH*NK*DD];
__device__ float g_qsim[BB*HH*NQ];
__device__ float g_ksim[BB*HH*NK];
__device__ int   g_cnt[BB*HH*NQ];
__device__ int   g_list[BB*HH*NQ*NK];
__device__ float g_ot[BB*LL*CC];

// ---------------- QKV GEMM: x[4096,512] @ Wqkv[512,1536] + b, scatter to q/k/v [B,H,L,D] ----------------
__global__ void __launch_bounds__(256) gemm_qkv(const float* __restrict__ A,
                                                const float* __restrict__ W,
                                                const float* __restrict__ bias) {
    __shared__ float As[16][68];
    __shared__ float Bs[16][64];
    const int K = CC, N = 3 * CC;
    int tid = threadIdx.x;
    int tx = tid & 15, ty = tid >> 4;
    int m0 = blockIdx.y * 64, n0 = blockIdx.x * 64;
    float acc[4][4] = {};
    for (int k0 = 0; k0 < K; k0 += 16) {
        #pragma unroll
        for (int i = 0; i < 4; i++) {
            int idx = tid + i * 256;
            int mm = idx >> 4, kk = idx & 15;
            As[kk][mm] = A[(m0 + mm) * K + k0 + kk];
        }
        #pragma unroll
        for (int i = 0; i < 4; i++) {
            int idx = tid + i * 256;
            int kk = idx >> 6, nn = idx & 63;
            Bs[kk][nn] = W[(k0 + kk) * N + n0 + nn];
        }
        __syncthreads();
        #pragma unroll
        for (int kk = 0; kk < 16; kk++) {
            float4 av = *(const float4*)&As[kk][ty * 4];
            float4 bv = *(const float4*)&Bs[kk][tx * 4];
            acc[0][0] += av.x * bv.x; acc[0][1] += av.x * bv.y; acc[0][2] += av.x * bv.z; acc[0][3] += av.x * bv.w;
            acc[1][0] += av.y * bv.x; acc[1][1] += av.y * bv.y; acc[1][2] += av.y * bv.z; acc[1][3] += av.y * bv.w;
            acc[2][0] += av.z * bv.x; acc[2][1] += av.z * bv.y; acc[2][2] += av.z * bv.z; acc[2][3] += av.z * bv.w;
            acc[3][0] += av.w * bv.x; acc[3][1] += av.w * bv.y; acc[3][2] += av.w * bv.z; acc[3][3] += av.w * bv.w;
        }
        __syncthreads();
    }
    #pragma unroll
    for (int r = 0; r < 4; r++) {
        int m = m0 + ty * 4 + r;
        int b = m >> 11, l = m & 2047;
        #pragma unroll
        for (int c = 0; c < 4; c++) {
            int j = n0 + tx * 4 + c;
            float val = acc[r][c] + bias[j];
            int t = j >> 9;
            int h = (j >> 6) & 7;
            int d = j & 63;
            float* dst = (t == 0) ? g_q : (t == 1) ? g_k : g_v;
            dst[(((b * HH + h) * LL) + l) * DD + d] = val;
        }
    }
}

// ---------------- block means + min-cosine ----------------
template<int BLK, bool ISQ>
__global__ void __launch_bounds__(128) block_meta(int nb) {
    __shared__ float tile[BLK * 65];
    __shared__ float mean[64];
    __shared__ float red[128];
    __shared__ float nm_s;
    const float* t = ISQ ? g_q : g_k;
    float* mout = ISQ ? g_qm : g_km;
    float* simout = ISQ ? g_qsim : g_ksim;
    int blkid = blockIdx.x % nb;
    int bh = blockIdx.x / nb;
    const float* base = t + (bh * LL + blkid * BLK) * DD;
    int tid = threadIdx.x;
    for (int i = tid; i < BLK * DD; i += 128) {
        int r = i >> 6, d = i & 63;
        tile[r * 65 + d] = base[i];
    }
    __syncthreads();
    if (tid < 64) {
        float s = 0.f;
        for (int r = 0; r < BLK; r++) s += tile[r * 65 + tid];
        s *= (1.0f / BLK);
        mean[tid] = s;
        mout[blockIdx.x * 64 + tid] = s;
    }
    __syncthreads();
    if (tid == 0) {
        float s = 0.f;
        for (int d = 0; d < 64; d++) s += mean[d] * mean[d];
        nm_s = sqrtf(s) + 1e-6f;
    }
    __syncthreads();
    float mycos = CUDART_INF_F;
    if (tid < BLK) {
        float dot = 0.f, nr = 0.f;
        for (int d = 0; d < 64; d++) {
            float xv = tile[tid * 65 + d];
            dot += xv * mean[d];
            nr += xv * xv;
        }
        mycos = dot / ((sqrtf(nr) + 1e-6f) * nm_s);
    }
    red[tid] = mycos;
    __syncthreads();
    for (int s = 64; s > 0; s >>= 1) {
        if (tid < s) red[tid] = fminf(red[tid], red[tid + s]);
        __syncthreads();
    }
    if (tid == 0) simout[blockIdx.x] = red[0];
}

// ---------------- pooled softmax + CDF keep mask -> compacted kept-block lists ----------------
// One CTA per (b,h). Phase 1: 512 threads compute 16x32 pooled dots.
// Phase 2: warp w sorts row w (bitonic via shfl), warp-scan CDF, ballot-compact.
__global__ void __launch_bounds__(512) mask_kernel() {
    __shared__ float qm_s[NQ * DD];
    __shared__ float km_s[NK * DD];
    __shared__ float pooled[NQ][NK + 1];
    __shared__ float ksim_s[NK];
    int bh = blockIdx.x;
    int tid = threadIdx.x;
    // load means
    for (int i = tid; i < NQ * DD; i += 512) qm_s[i] = g_qm[bh * NQ * DD + i];
    for (int i = tid; i < NK * DD; i += 512) km_s[i] = g_km[bh * NK * DD + i];
    if (tid < NK) ksim_s[tid] = g_ksim[bh * NK + tid];
    __syncthreads();
    {
        int qi = tid >> 5, j = tid & 31;
        const float* qv = &qm_s[qi * DD];
        const float* kv = &km_s[j * DD];
        float dot = 0.f;
        #pragma unroll
        for (int d = 0; d < DD; d++) dot += qv[d] * kv[d];
        pooled[qi][j] = dot * 0.125f;
    }
    __syncthreads();
    int w = tid >> 5;        // warp = Q row
    int lane = tid & 31;
    float v = pooled[w][lane];
    // softmax over the row (warp)
    float mx = v;
    #pragma unroll
    for (int s = 16; s > 0; s >>= 1) mx = fmaxf(mx, __shfl_xor_sync(0xffffffffu, mx, s));
    float p = expf(v - mx);
    float sum = p;
    #pragma unroll
    for (int s = 16; s > 0; s >>= 1) sum += __shfl_xor_sync(0xffffffffu, sum, s);
    p /= sum;
    // bitonic sort descending (stable tie-break by ascending index)
    float sv = p;
    int si = lane;
    #pragma unroll
    for (int k = 2; k <= 32; k <<= 1) {
        #pragma unroll
        for (int j = k >> 1; j > 0; j >>= 1) {
            float ov = __shfl_xor_sync(0xffffffffu, sv, j);
            int   oi = __shfl_xor_sync(0xffffffffu, si, j);
            bool iprecede = (sv > ov) || (sv == ov && si < oi);
            bool lower = ((lane & j) == 0);
            bool dir = ((lane & k) == 0);
            bool keep_mine = ((lower == iprecede) == dir);
            if (!keep_mine) { sv = ov; si = oi; }
        }
    }
    // inclusive scan of sorted probs
    float csum = sv;
    #pragma unroll
    for (int s = 1; s < 32; s <<= 1) {
        float t = __shfl_up_sync(0xffffffffu, csum, s);
        if (lane >= s) csum += t;
    }
    bool kept_sorted = (csum - sv) < 0.98f;
    unsigned keepmask = __reduce_or_sync(0xffffffffu, kept_sorted ? (1u << si) : 0u);
    // fallback: non-self-similar blocks never pruned
    bool qself = g_qsim[bh * NQ + w] > 0.6f;
    bool kself = ksim_s[lane] > 0.6f;
    bool fin = ((keepmask >> lane) & 1u) || !qself || !kself;
    unsigned fmask = __ballot_sync(0xffffffffu, fin);
    int pos = __popc(fmask & ((1u << lane) - 1u));
    int rowid = bh * NQ + w;
    if (fin) g_list[rowid * NK + pos] = lane;
    if (lane == 0) g_cnt[rowid] = __popc(fmask);
}

// ---------------- masked flash attention: 2 threads per Q row, 2 keys per iter ----------------
__global__ void __launch_bounds__(256) attn_kernel() {
    __shared__ float Ks[64 * 64];
    __shared__ float Vs[64 * 64];
    int bh = blockIdx.y;     // 0..15
    int qb = blockIdx.x;     // 0..15
    int tid = threadIdx.x;   // 0..255
    int r = tid >> 1;        // 0..127 (Q row within block)
    int half = (tid & 1) * 32;
    int row = qb * BLKQ + r;
    const float* qp = g_q + (bh * LL + row) * DD + half;
    float qreg[32];
    #pragma unroll
    for (int i = 0; i < 8; i++) {
        float4 v = *(const float4*)(qp + i * 4);
        qreg[4*i] = v.x; qreg[4*i+1] = v.y; qreg[4*i+2] = v.z; qreg[4*i+3] = v.w;
    }
    float m = -CUDART_INF_F, l = 0.f;
    float acc[32];
    #pragma unroll
    for (int d = 0; d < 32; d++) acc[d] = 0.f;
    int cnt = g_cnt[bh * NQ + qb];
    const int* __restrict__ list = g_list + (bh * NQ + qb) * NK;

    for (int it = 0; it < cnt; it++) {
        int kb = list[it];
        __syncthreads();
        const float4* Kg = (const float4*)(g_k + (bh * LL + kb * BLKK) * DD);
        const float4* Vg = (const float4*)(g_v + (bh * LL + kb * BLKK) * DD);
        #pragma unroll
        for (int i = 0; i < 4; i++) {
            ((float4*)Ks)[tid + i * 256] = Kg[tid + i * 256];
            ((float4*)Vs)[tid + i * 256] = Vg[tid + i * 256];
        }
        __syncthreads();
        #pragma unroll 4
        for (int j = 0; j < 64; j += 2) {
            const float* k0 = &Ks[j * 64 + half];
            const float* k1 = &Ks[(j + 1) * 64 + half];
            float s0 = 0.f, s1 = 0.f;
            #pragma unroll
            for (int i = 0; i < 8; i++) {
                float4 a = *(const float4*)(k0 + 4 * i);
                float4 b = *(const float4*)(k1 + 4 * i);
                s0 += qreg[4*i]*a.x + qreg[4*i+1]*a.y + qreg[4*i+2]*a.z + qreg[4*i+3]*a.w;
                s1 += qreg[4*i]*b.x + qreg[4*i+1]*b.y + qreg[4*i+2]*b.z + qreg[4*i+3]*b.w;
            }
            s0 += __shfl_xor_sync(0xffffffffu, s0, 1);
            s1 += __shfl_xor_sync(0xffffffffu, s1, 1);
            s0 *= 0.125f; s1 *= 0.125f;
            float mn = fmaxf(m, fmaxf(s0, s1));
            if (mn > m) {
                float f = __expf(m - mn);
                l *= f;
                #pragma unroll
                for (int d = 0; d < 32; d++) acc[d] *= f;
                m = mn;
            }
            float p0 = __expf(s0 - m);
            float p1 = __expf(s1 - m);
            l += p0 + p1;
            const float* v0 = &Vs[j * 64 + half];
            const float* v1 = &Vs[(j + 1) * 64 + half];
            #pragma unroll
            for (int i = 0; i < 8; i++) {
                float4 a = *(const float4*)(v0 + 4 * i);
                float4 b = *(const float4*)(v1 + 4 * i);
                acc[4*i]   += p0 * a.x + p1 * b.x;
                acc[4*i+1] += p0 * a.y + p1 * b.y;
                acc[4*i+2] += p0 * a.z + p1 * b.z;
                acc[4*i+3] += p0 * a.w + p1 * b.w;
            }
        }
    }
    float inv = 1.0f / l;
    int b = bh >> 3, h = bh & 7;
    float* op = g_ot + (b * LL + row) * CC + h * DD + half;
    #pragma unroll
    for (int i = 0; i < 8; i++) {
        float4 v;
        v.x = acc[4*i] * inv; v.y = acc[4*i+1] * inv;
        v.z = acc[4*i+2] * inv; v.w = acc[4*i+3] * inv;
        *(float4*)(op + 4 * i) = v;
    }
}

// ---------------- output projection: ot[4096,512] @ Wproj[512,512] + b ----------------
__global__ void __launch_bounds__(256) gemm_proj(const float* __restrict__ W,
                                                 const float* __restrict__ bias,
                                                 float* __restrict__ out) {
    __shared__ float As[16][68];
    __shared__ float Bs[16][64];
    const int K = CC, N = CC;
    const float* __restrict__ A = g_ot;
    int tid = threadIdx.x;
    int tx = tid & 15, ty = tid >> 4;
    int m0 = blockIdx.y * 64, n0 = blockIdx.x * 64;
    float acc[4][4] = {};
    for (int k0 = 0; k0 < K; k0 += 16) {
        #pragma unroll
        for (int i = 0; i < 4; i++) {
            int idx = tid + i * 256;
            int mm = idx >> 4, kk = idx & 15;
            As[kk][mm] = A[(m0 + mm) * K + k0 + kk];
        }
        #pragma unroll
        for (int i = 0; i < 4; i++) {
            int idx = tid + i * 256;
            int kk = idx >> 6, nn = idx & 63;
            Bs[kk][nn] = W[(k0 + kk) * N + n0 + nn];
        }
        __syncthreads();
        #pragma unroll
        for (int kk = 0; kk < 16; kk++) {
            float4 av = *(const float4*)&As[kk][ty * 4];
            float4 bv = *(const float4*)&Bs[kk][tx * 4];
            acc[0][0] += av.x * bv.x; acc[0][1] += av.x * bv.y; acc[0][2] += av.x * bv.z; acc[0][3] += av.x * bv.w;
            acc[1][0] += av.y * bv.x; acc[1][1] += av.y * bv.y; acc[1][2] += av.y * bv.z; acc[1][3] += av.y * bv.w;
            acc[2][0] += av.z * bv.x; acc[2][1] += av.z * bv.y; acc[2][2] += av.z * bv.z; acc[2][3] += av.z * bv.w;
            acc[3][0] += av.w * bv.x; acc[3][1] += av.w * bv.y; acc[3][2] += av.w * bv.z; acc[3][3] += av.w * bv.w;
        }
        __syncthreads();
    }
    #pragma unroll
    for (int r = 0; r < 4; r++) {
        int m = m0 + ty * 4 + r;
        #pragma unroll
        for (int c = 0; c < 4; c++) {
            int j = n0 + tx * 4 + c;
            out[m * N + j] = acc[r][c] + bias[j];
        }
    }
}

extern "C" void kernel_launch(void* const* d_in, const int* in_sizes, int n_in,
                              void* d_out, int out_size) {
    const float* x     = (const float*)d_in[0];
    const float* Wqkv  = (const float*)d_in[1];
    const float* bqkv  = (const float*)d_in[2];
    const float* Wproj = (const float*)d_in[3];
    const float* bproj = (const float*)d_in[4];
    float* out = (float*)d_out;

    dim3 g1(24, 64);                       // N=1536/64, M=4096/64
    gemm_qkv<<<g1, 256>>>(x, Wqkv, bqkv);

    block_meta<BLKQ, true><<<BB * HH * NQ, 128>>>(NQ);
    block_meta<BLKK, false><<<BB * HH * NK, 128>>>(NK);

    mask_kernel<<<BB * HH, 512>>>();

    dim3 ga(NQ, BB * HH);
    attn_kernel<<<ga, 256>>>();

    dim3 g2(8, 64);                        // N=512/64, M=4096/64
    gemm_proj<<<g2, 256>>>(Wproj, bproj, out);
}